// round 13
// baseline (speedup 1.0000x reference)
#include <cuda_runtime.h>
#include <math.h>

#define NLAB 17
#define LTOT 19
#define SEQ  256
#define MAXB 8192
#define LN2  0.69314718055994531f
#define FULL 0xffffffffu

__device__ int   d_sorted[MAXB];
__device__ float d_gold[MAXB];

// dense predecessor states (fwd gather): {O, E-*, S-*}
__constant__ signed char cDP[9] = {0,3,4,7,8,11,12,15,16};
// dense target states (bwd gather): {O, B-*, S-*}
__constant__ signed char cDT[9] = {0,1,4,5,8,9,12,13,16};

// One-block fused sort, 1024 threads: smem histogram, warp-0 register
// suffix-scan of the 256 bins, scatter. d_sorted = descending length.
__global__ __launch_bounds__(1024)
void crf_sched(const int* __restrict__ lens, int B)
{
    __shared__ int h[SEQ];
    const int t = threadIdx.x;
    if (t < SEQ) h[t] = 0;
    __syncthreads();
    for (int i = t; i < B; i += 1024) atomicAdd(&h[lens[i] - 1], 1);
    __syncthreads();
    if (t < 32) {
        const int base = t * 8;
        int v[8];
        int s = 0;
        #pragma unroll
        for (int k = 7; k >= 0; --k) { v[k] = s; s += h[base + k]; }
        int x = s;
        #pragma unroll
        for (int off = 1; off < 32; off <<= 1) {
            int y = __shfl_down_sync(FULL, x, off);
            if (t + off < 32) x += y;
        }
        int e = x - s;
        #pragma unroll
        for (int k = 0; k < 8; ++k) h[base + k] = v[k] + e;
    }
    __syncthreads();
    for (int i = t; i < B; i += 1024) {
        int r = atomicAdd(&h[lens[i] - 1], 1);
        d_sorted[r] = i;
    }
}

// Gold score: one warp per row, lanes stride the sequence (high MLP, full occ).
__global__ __launch_bounds__(256)
void crf_gold(const float* __restrict__ logits,
              const int*   __restrict__ labels,
              const int*   __restrict__ lens,
              const float* __restrict__ transition, int B)
{
    __shared__ float sT[LTOT * LTOT];
    for (int i = threadIdx.x; i < LTOT * LTOT; i += 256) sT[i] = transition[i];
    __syncthreads();

    const int lane = threadIdx.x & 31;
    const int b = blockIdx.x * 8 + (threadIdx.x >> 5);
    if (b >= B) return;

    const float* lg  = logits + (size_t)b * (SEQ * NLAB);
    const int*   lab = labels + (size_t)b * SEQ;
    const int    len = lens[b];

    float g = 0.f;
    for (int t = lane; t < len; t += 32) {
        int lt = lab[t];
        int lp = t ? lab[t - 1] : (LTOT - 2);
        g += lg[t * NLAB + lt] + sT[lt * LTOT + lp];
    }
    if (lane == 0) g += sT[(LTOT - 1) * LTOT + lab[len - 1]];
    #pragma unroll
    for (int o = 16; o; o >>= 1) g += __shfl_xor_sync(FULL, g, o);
    if (lane == 0) d_gold[b] = g;
}

#define RESC() { \
    float _mx = fmaxf(fmaxf(p0,p1), fmaxf(p2, fmaxf(p3,p4))); \
    _mx = fmaxf(_mx, __shfl_xor_sync(FULL,_mx,1,4)); \
    _mx = fmaxf(_mx, __shfl_xor_sync(FULL,_mx,2,4)); \
    int _eb = (int)(__float_as_uint(_mx)>>23); \
    float _sc = __uint_as_float((unsigned)(254-_eb)<<23); \
    p0*=_sc; p1*=_sc; p2*=_sc; p3*=_sc; p4*=_sc; C += _eb-127; }

#define FLOAD(R, T) { const float* _a = lp5 + (T)*NLAB; \
    R[0]=__ldg(_a+0); R[1]=__ldg(_a+1); R[2]=__ldg(_a+2); \
    R[3]=__ldg(_a+3); R[4]=__ldg(_a+4); }

#define BLOAD(R, K) { int _tt = lenm1 - (K); if (_tt < 0) _tt = 0; \
    const float* _a = lp5 + _tt*NLAB; \
    R[0]=__ldg(_a+0); R[1]=__ldg(_a+1); R[2]=__ldg(_a+2); \
    R[3]=__ldg(_a+3); R[4]=__ldg(_a+4); }

// tree-form 9-wide dot products: 3 parallel partials -> depth ~20 cyc
#define DENSE9() \
    float _u0=fmaf(w0[3],_Q3, w0[0]*_Q0); \
    float _v0=fmaf(w0[4],_Q4, w0[1]*_Q1); \
    float _t0=fmaf(w0[5],_Q5, w0[2]*_Q2); \
    float _u1=fmaf(w1[3],_Q3, w1[0]*_Q0); \
    float _v1=fmaf(w1[4],_Q4, w1[1]*_Q1); \
    float _t1=fmaf(w1[5],_Q5, w1[2]*_Q2); \
    float _u2=fmaf(w2[3],_Q3, w2[0]*_Q0); \
    float _v2=fmaf(w2[4],_Q4, w2[1]*_Q1); \
    float _t2=fmaf(w2[5],_Q5, w2[2]*_Q2); \
    _u0=fmaf(w0[6],_Q6,_u0); _v0=fmaf(w0[7],_Q7,_v0); _t0=fmaf(w0[8],_Q8,_t0); \
    _u1=fmaf(w1[6],_Q6,_u1); _v1=fmaf(w1[7],_Q7,_v1); _t1=fmaf(w1[8],_Q8,_t1); \
    _u2=fmaf(w2[6],_Q6,_u2); _v2=fmaf(w2[7],_Q7,_v2); _t2=fmaf(w2[8],_Q8,_t2); \
    float _S0=(_u0+_v0)+_t0; \
    float _S1=(_u1+_v1)+_t1; \
    float _S2=(_u2+_v2)+_t2;

#define FSTEP(R, T) if ((T) < warpM) { \
    float _e0=__expf(R[0]), _e1=__expf(R[1]), _e2=__expf(R[2]); \
    float _e3=__expf(R[3]), _e4=__expf(R[4]); \
    float _Q0=__shfl_sync(FULL,p0,base+0); \
    float _Q1=__shfl_sync(FULL,p3,base+0); \
    float _Q2=__shfl_sync(FULL,p0,base+1); \
    float _Q3=__shfl_sync(FULL,p3,base+1); \
    float _Q4=__shfl_sync(FULL,p0,base+2); \
    float _Q5=__shfl_sync(FULL,p3,base+2); \
    float _Q6=__shfl_sync(FULL,p0,base+3); \
    float _Q7=__shfl_sync(FULL,p3,base+3); \
    float _Q8=__shfl_sync(FULL,p4,base+3); \
    DENSE9() \
    float _nI = fmaf(wII,p2, wIB*p1); \
    float _nE = fmaf(wEI,p2, wEB*p1); \
    bool _act = (T) < myM; \
    p0 = _act ? _e0*_S0 : p0; \
    p1 = _act ? _e1*_S1 : p1; \
    p2 = _act ? _e2*_nI : p2; \
    p3 = _act ? _e3*_nE : p3; \
    p4 = _act ? _e4*_S2 : p4; \
    if (((T)&7)==0) RESC() }

#define BSTEP(R, K) if ((K) < warpS) { \
    float _u0l=p0*__expf(R[0]); \
    float _u1l=p1*__expf(R[1]); \
    float _u2l=p2*__expf(R[2]); \
    float _u3l=p3*__expf(R[3]); \
    float _u4l=p4*__expf(R[4]); \
    float _Q0=__shfl_sync(FULL,_u0l,base+0); \
    float _Q1=__shfl_sync(FULL,_u1l,base+0); \
    float _Q2=__shfl_sync(FULL,_u0l,base+1); \
    float _Q3=__shfl_sync(FULL,_u1l,base+1); \
    float _Q4=__shfl_sync(FULL,_u0l,base+2); \
    float _Q5=__shfl_sync(FULL,_u1l,base+2); \
    float _Q6=__shfl_sync(FULL,_u0l,base+3); \
    float _Q7=__shfl_sync(FULL,_u1l,base+3); \
    float _Q8=__shfl_sync(FULL,_u4l,base+3); \
    DENSE9() \
    float _nB = fmaf(wEB,_u3l, wIB*_u2l); \
    float _nI = fmaf(wEI,_u3l, wII*_u2l); \
    bool _act = (K) < mySteps; \
    p0 = _act ? _S0 : p0; \
    p1 = _act ? _nB : p1; \
    p2 = _act ? _nI : p2; \
    p3 = _act ? _S1 : p3; \
    p4 = _act ? _S2 : p4; \
    if (((K)&7)==7) RESC() }

// Block = 8 warps = 4 (fwd,bwd) pairs, 8 rows per pair (4 lanes per row).
// Serpentine group assignment balances per-SM makespan across grid=148.
// Triple-buffered 4-step tiles: load-to-use distance = 8 steps (~450 cyc).
__global__ __launch_bounds__(256)
void crf_main(const float* __restrict__ logits,
              const int*   __restrict__ lens,
              const float* __restrict__ transition,
              float* __restrict__ out, int B)
{
    __shared__ float sT[LTOT*LTOT];
    __shared__ float sA[4][8][20];
    __shared__ int   sC[4][8];

    for (int i = threadIdx.x; i < LTOT*LTOT; i += 256) sT[i] = transition[i];
    __syncthreads();

    const int lane = threadIdx.x & 31;
    const int wId  = threadIdx.x >> 5;
    const int q    = wId >> 1;
    const bool isB = wId & 1;
    const int g    = lane & 3;
    const int r    = lane >> 2;
    const int base = lane & ~3;

    const int nG  = (B + 7) >> 3;
    const int per = gridDim.x;
    const int G   = q * per + ((q & 1) ? (per - 1 - (int)blockIdx.x)
                                       : (int)blockIdx.x);
    int rank = G * 8 + r;
    const bool valid = (G < nG) && (rank < B);
    if (!valid) rank = B - 1;
    const int b   = d_sorted[rank];
    const int len = lens[b];
    const int m   = (len + 1) >> 1;

    const float* lg  = logits + (size_t)b * (SEQ*NLAB);
    const int    s0  = 4*g;
    const float* lp5 = lg + s0;

    float p0,p1,p2,p3,p4;
    int C = 0;

    if (!isB) {
        // ---------------- FORWARD: a_{m-1} ---------------------------------
        float w0[9], w1[9], w2[9];
        #pragma unroll
        for (int k = 0; k < 9; ++k) {
            int pr = cDP[k];
            w0[k] = expf(sT[s0*LTOT + pr]);
            w1[k] = expf(sT[(s0+1)*LTOT + pr]);
            w2[k] = (g==3) ? expf(sT[16*LTOT + pr]) : 0.f;
        }
        const float wIB = expf(sT[(s0+2)*LTOT + (s0+1)]);
        const float wII = expf(sT[(s0+2)*LTOT + (s0+2)]);
        const float wEB = expf(sT[(s0+3)*LTOT + (s0+1)]);
        const float wEI = expf(sT[(s0+3)*LTOT + (s0+2)]);

        {   // t = 0
            float wst4 = (g==3) ? expf(sT[16*LTOT + 17]) : 0.f;
            p0 = __expf(__ldg(lp5+0)) * expf(sT[s0*LTOT + 17]);
            p1 = __expf(__ldg(lp5+1)) * expf(sT[(s0+1)*LTOT + 17]);
            p2 = __expf(__ldg(lp5+2)) * expf(sT[(s0+2)*LTOT + 17]);
            p3 = __expf(__ldg(lp5+3)) * expf(sT[(s0+3)*LTOT + 17]);
            p4 = __expf(__ldg(lp5+4)) * wst4;
            RESC()
        }

        const int myM   = m;
        const int warpM = __reduce_max_sync(FULL, myM);

        float RA[4][5], RB[4][5], RC[4][5];
        FLOAD(RA[0],1) FLOAD(RA[1],2) FLOAD(RA[2],3) FLOAD(RA[3],4)
        FLOAD(RB[0],5) FLOAD(RB[1],6) FLOAD(RB[2],7) FLOAD(RB[3],8)
        for (int t0 = 1; t0 < warpM; t0 += 12) {
            FLOAD(RC[0],t0+8)  FLOAD(RC[1],t0+9)  FLOAD(RC[2],t0+10) FLOAD(RC[3],t0+11)
            FSTEP(RA[0],t0)    FSTEP(RA[1],t0+1)  FSTEP(RA[2],t0+2)  FSTEP(RA[3],t0+3)
            FLOAD(RA[0],t0+12) FLOAD(RA[1],t0+13) FLOAD(RA[2],t0+14) FLOAD(RA[3],t0+15)
            FSTEP(RB[0],t0+4)  FSTEP(RB[1],t0+5)  FSTEP(RB[2],t0+6)  FSTEP(RB[3],t0+7)
            FLOAD(RB[0],t0+16) FLOAD(RB[1],t0+17) FLOAD(RB[2],t0+18) FLOAD(RB[3],t0+19)
            FSTEP(RC[0],t0+8)  FSTEP(RC[1],t0+9)  FSTEP(RC[2],t0+10) FSTEP(RC[3],t0+11)
        }

        sA[q][r][s0+0]=p0; sA[q][r][s0+1]=p1;
        sA[q][r][s0+2]=p2; sA[q][r][s0+3]=p3;
        if (g==3) sA[q][r][16]=p4;
        if (g==0) sC[q][r]=C;
        asm volatile("bar.sync %0, %1;" :: "r"(1+q), "r"(64) : "memory");
    } else {
        // ---------------- BACKWARD: b_m -------------------------------------
        float w0[9], w1[9], w2[9];
        #pragma unroll
        for (int k = 0; k < 9; ++k) {
            int dt = cDT[k];
            w0[k] = expf(sT[dt*LTOT + s0]);
            w1[k] = expf(sT[dt*LTOT + (s0+3)]);
            w2[k] = (g==3) ? expf(sT[dt*LTOT + 16]) : 0.f;
        }
        const float wIB = expf(sT[(s0+2)*LTOT + (s0+1)]);
        const float wII = expf(sT[(s0+2)*LTOT + (s0+2)]);
        const float wEB = expf(sT[(s0+3)*LTOT + (s0+1)]);
        const float wEI = expf(sT[(s0+3)*LTOT + (s0+2)]);

        p0 = expf(sT[18*LTOT + s0]);
        p1 = expf(sT[18*LTOT + (s0+1)]);
        p2 = expf(sT[18*LTOT + (s0+2)]);
        p3 = expf(sT[18*LTOT + (s0+3)]);
        p4 = (g==3) ? expf(sT[18*LTOT + 16]) : 0.f;

        const int mySteps = len - m;
        const int warpS   = __reduce_max_sync(FULL, mySteps);
        const int lenm1   = len - 1;

        float RA[4][5], RB[4][5], RC[4][5];
        BLOAD(RA[0],0) BLOAD(RA[1],1) BLOAD(RA[2],2) BLOAD(RA[3],3)
        BLOAD(RB[0],4) BLOAD(RB[1],5) BLOAD(RB[2],6) BLOAD(RB[3],7)
        for (int k0 = 0; k0 < warpS; k0 += 12) {
            BLOAD(RC[0],k0+8)  BLOAD(RC[1],k0+9)  BLOAD(RC[2],k0+10) BLOAD(RC[3],k0+11)
            BSTEP(RA[0],k0)    BSTEP(RA[1],k0+1)  BSTEP(RA[2],k0+2)  BSTEP(RA[3],k0+3)
            BLOAD(RA[0],k0+12) BLOAD(RA[1],k0+13) BLOAD(RA[2],k0+14) BLOAD(RA[3],k0+15)
            BSTEP(RB[0],k0+4)  BSTEP(RB[1],k0+5)  BSTEP(RB[2],k0+6)  BSTEP(RB[3],k0+7)
            BLOAD(RB[0],k0+16) BLOAD(RB[1],k0+17) BLOAD(RB[2],k0+18) BLOAD(RB[3],k0+19)
            BSTEP(RC[0],k0+8)  BSTEP(RC[1],k0+9)  BSTEP(RC[2],k0+10) BSTEP(RC[3],k0+11)
        }

        asm volatile("bar.sync %0, %1;" :: "r"(1+q), "r"(64) : "memory");

        float ss = p0 * sA[q][r][s0+0];
        ss = fmaf(p1, sA[q][r][s0+1], ss);
        ss = fmaf(p2, sA[q][r][s0+2], ss);
        ss = fmaf(p3, sA[q][r][s0+3], ss);
        ss = fmaf(p4, sA[q][r][s0+4], ss);
        ss += __shfl_xor_sync(FULL, ss, 1, 4);
        ss += __shfl_xor_sync(FULL, ss, 2, 4);

        if (g==0 && valid) {
            int cT = C + sC[q][r];
            out[b] = d_gold[b] - ((float)cT*LN2 + logf(ss));
        }
    }
}

extern "C" void kernel_launch(void* const* d_in, const int* in_sizes, int n_in,
                              void* d_out, int out_size)
{
    const float* logits     = (const float*)d_in[0];
    const int*   labels     = (const int*)  d_in[1];
    const int*   lens       = (const int*)  d_in[2];
    const float* transition = (const float*)d_in[3];
    float*       out        = (float*)d_out;

    int B = in_sizes[2];

    crf_sched<<<1, 1024>>>(lens, B);
    crf_gold<<<(B + 7) / 8, 256>>>(logits, labels, lens, transition, B);

    int nGroups = (B + 7) / 8;
    int grid = (nGroups + 3) / 4;
    if (grid < 148) grid = 148;
    crf_main<<<grid, 256>>>(logits, lens, transition, out, B);
}

// round 14
// speedup vs baseline: 1.0215x; 1.0215x over previous
#include <cuda_runtime.h>
#include <math.h>
#include <stdint.h>

#define NLAB 17
#define LTOT 19
#define SEQ  256
#define MAXB 8192
#define LN2  0.69314718055994531f
#define FULL 0xffffffffu

#define ROWF 140                 // padded per-row stride in staged tile (floats)
#define BUFF (8*ROWF)            // one tile buffer: 8 rows x 140 = 1120 floats
#define WBUF (2*BUFF)            // double buffer per warp

// dynamic smem layout (float offsets)
#define OFF_T   (8*WBUF)                  // transition matrix (361)
#define OFF_A   (OFF_T + LTOT*LTOT)       // sA: 4 pairs x 8 rows x 20
#define OFF_G   (OFF_A + 4*8*20)
#define OFF_C   (OFF_G + 32)
#define OFF_P   (OFF_C + 32 + 1)          // 18986: even -> 8B aligned ptrs
#define SMEM_FLOATS (OFF_P + 2*64)
#define SMEM_BYTES  (SMEM_FLOATS * 4)

__device__ int d_sorted[MAXB];

__constant__ signed char cDP[9] = {0,3,4,7,8,11,12,15,16};
__constant__ signed char cDT[9] = {0,1,4,5,8,9,12,13,16};

// One-block fused sort: histogram + warp-0 register suffix scan + scatter.
__global__ __launch_bounds__(1024)
void crf_sched(const int* __restrict__ lens, int B)
{
    __shared__ int h[SEQ];
    const int t = threadIdx.x;
    if (t < SEQ) h[t] = 0;
    __syncthreads();
    for (int i = t; i < B; i += 1024) atomicAdd(&h[lens[i] - 1], 1);
    __syncthreads();
    if (t < 32) {
        const int base = t * 8;
        int v[8]; int s = 0;
        #pragma unroll
        for (int k = 7; k >= 0; --k) { v[k] = s; s += h[base + k]; }
        int x = s;
        #pragma unroll
        for (int off = 1; off < 32; off <<= 1) {
            int y = __shfl_down_sync(FULL, x, off);
            if (t + off < 32) x += y;
        }
        int e = x - s;
        #pragma unroll
        for (int k = 0; k < 8; ++k) h[base + k] = v[k] + e;
    }
    __syncthreads();
    for (int i = t; i < B; i += 1024) {
        int r = atomicAdd(&h[lens[i] - 1], 1);
        d_sorted[r] = i;
    }
}

#define CP16(dst_u32, src_ptr) \
    asm volatile("cp.async.ca.shared.global [%0], [%1], 16;" \
                 :: "r"(dst_u32), "l"(src_ptr))
#define CPCOMMIT() asm volatile("cp.async.commit_group;")
#define CPWAIT1()  asm volatile("cp.async.wait_group 1;")

// Coalesced stage of one 8-step tile (8 rows x 136 floats = 272 float4).
__device__ __forceinline__ void stage_tile(const float* const* rp,
                                           uint32_t dstb, int k8, int lane)
{
    #pragma unroll
    for (int it = 0; it < 9; ++it) {
        int idx = it * 32 + lane;
        if (idx < 272) {
            int rr = (int)((unsigned)idx / 34u);
            int jj = idx - rr * 34;
            const float* sp = rp[rr] + k8 * 17 + jj * 4;
            CP16(dstb + (uint32_t)(rr * ROWF + jj * 4) * 4u, sp);
        }
    }
}

#define RESC() { \
    float _mx = fmaxf(fmaxf(p0,p1), fmaxf(p2, fmaxf(p3,p4))); \
    _mx = fmaxf(_mx, __shfl_xor_sync(FULL,_mx,1,4)); \
    _mx = fmaxf(_mx, __shfl_xor_sync(FULL,_mx,2,4)); \
    int _eb = (int)(__float_as_uint(_mx)>>23); \
    float _sc = __uint_as_float((unsigned)(254-_eb)<<23); \
    p0*=_sc; p1*=_sc; p2*=_sc; p3*=_sc; p4*=_sc; C += _eb-127; }

#define DENSE9() \
    float _u0=fmaf(w0[3],_Q3, w0[0]*_Q0); \
    float _v0=fmaf(w0[4],_Q4, w0[1]*_Q1); \
    float _t0=fmaf(w0[5],_Q5, w0[2]*_Q2); \
    float _u1=fmaf(w1[3],_Q3, w1[0]*_Q0); \
    float _v1=fmaf(w1[4],_Q4, w1[1]*_Q1); \
    float _t1=fmaf(w1[5],_Q5, w1[2]*_Q2); \
    float _u2=fmaf(w2[3],_Q3, w2[0]*_Q0); \
    float _v2=fmaf(w2[4],_Q4, w2[1]*_Q1); \
    float _t2=fmaf(w2[5],_Q5, w2[2]*_Q2); \
    _u0=fmaf(w0[6],_Q6,_u0); _v0=fmaf(w0[7],_Q7,_v0); _t0=fmaf(w0[8],_Q8,_t0); \
    _u1=fmaf(w1[6],_Q6,_u1); _v1=fmaf(w1[7],_Q7,_v1); _t1=fmaf(w1[8],_Q8,_t1); \
    _u2=fmaf(w2[6],_Q6,_u2); _v2=fmaf(w2[7],_Q7,_v2); _t2=fmaf(w2[8],_Q8,_t2); \
    float _S0=(_u0+_v0)+_t0; \
    float _S1=(_u1+_v1)+_t1; \
    float _S2=(_u2+_v2)+_t2;

// forward step at absolute time T, reading staged tile cb at local step LT
#define FSTEP(cb, LT, T) if ((T) < warpM) { \
    const float* _b = (cb) + roff + (LT)*17; \
    float _e0=__expf(_b[0]), _e1=__expf(_b[1]), _e2=__expf(_b[2]); \
    float _e3=__expf(_b[3]), _e4=__expf(_b[4]); \
    float _Q0=__shfl_sync(FULL,p0,base+0); \
    float _Q1=__shfl_sync(FULL,p3,base+0); \
    float _Q2=__shfl_sync(FULL,p0,base+1); \
    float _Q3=__shfl_sync(FULL,p3,base+1); \
    float _Q4=__shfl_sync(FULL,p0,base+2); \
    float _Q5=__shfl_sync(FULL,p3,base+2); \
    float _Q6=__shfl_sync(FULL,p0,base+3); \
    float _Q7=__shfl_sync(FULL,p3,base+3); \
    float _Q8=__shfl_sync(FULL,p4,base+3); \
    DENSE9() \
    float _nI = fmaf(wII,p2, wIB*p1); \
    float _nE = fmaf(wEI,p2, wEB*p1); \
    bool _act = ((T) >= 1) && ((T) < myM); \
    p0 = _act ? _e0*_S0 : p0; \
    p1 = _act ? _e1*_S1 : p1; \
    p2 = _act ? _e2*_nI : p2; \
    p3 = _act ? _e3*_nE : p3; \
    p4 = _act ? _e4*_S2 : p4; }

// backward step at absolute time T
#define BSTEP(cb, LT, T) if ((T) <= warpT1) { \
    const float* _b = (cb) + roff + (LT)*17; \
    float _u0l=p0*__expf(_b[0]); \
    float _u1l=p1*__expf(_b[1]); \
    float _u2l=p2*__expf(_b[2]); \
    float _u3l=p3*__expf(_b[3]); \
    float _u4l=p4*__expf(_b[4]); \
    float _Q0=__shfl_sync(FULL,_u0l,base+0); \
    float _Q1=__shfl_sync(FULL,_u1l,base+0); \
    float _Q2=__shfl_sync(FULL,_u0l,base+1); \
    float _Q3=__shfl_sync(FULL,_u1l,base+1); \
    float _Q4=__shfl_sync(FULL,_u0l,base+2); \
    float _Q5=__shfl_sync(FULL,_u1l,base+2); \
    float _Q6=__shfl_sync(FULL,_u0l,base+3); \
    float _Q7=__shfl_sync(FULL,_u1l,base+3); \
    float _Q8=__shfl_sync(FULL,_u4l,base+3); \
    DENSE9() \
    float _nB = fmaf(wEB,_u3l, wIB*_u2l); \
    float _nI = fmaf(wEI,_u3l, wII*_u2l); \
    bool _act = ((T) >= myM) && ((T) <= lenm1); \
    p0 = _act ? _S0 : p0; \
    p1 = _act ? _nB : p1; \
    p2 = _act ? _nI : p2; \
    p3 = _act ? _S1 : p3; \
    p4 = _act ? _S2 : p4; }

// Block = 8 warps = 4 (fwd,bwd) MITM pairs, 8 rows/pair (4 lanes/row).
// Logit tiles staged via cp.async (coalesced) into per-warp smem buffers.
__global__ __launch_bounds__(256)
void crf_main(const float* __restrict__ logits,
              const int*   __restrict__ labels,
              const int*   __restrict__ lens,
              const float* __restrict__ transition,
              float* __restrict__ out, int B)
{
    extern __shared__ float dyn[];
    float* sT = dyn + OFF_T;

    for (int i = threadIdx.x; i < LTOT*LTOT; i += 256) sT[i] = transition[i];

    const int lane = threadIdx.x & 31;
    const int wId  = threadIdx.x >> 5;
    const int q    = wId >> 1;
    const bool isB = wId & 1;
    const int g    = lane & 3;
    const int r    = lane >> 2;
    const int base = lane & ~3;

    const int nG  = (B + 7) >> 3;
    const int per = gridDim.x;
    const int G   = q * per + ((q & 1) ? (per - 1 - (int)blockIdx.x)
                                       : (int)blockIdx.x);
    int rank = G * 8 + r;
    const bool valid = (G < nG) && (rank < B);
    if (!valid) rank = B - 1;
    const int b   = d_sorted[rank];
    const int len = lens[b];
    const int m   = (len + 1) >> 1;

    const float* lg  = logits + (size_t)b * (SEQ*NLAB);
    const int*   lab = labels + (size_t)b * SEQ;
    const int    s0  = 4*g;
    const int    roff = r*ROWF + s0;

    float* wbuf = dyn + wId * WBUF;
    uint32_t bufb = (uint32_t)__cvta_generic_to_shared(wbuf);
    const float** rp = (const float**)(dyn + OFF_P) + wId * 8;
    if (g == 0) rp[r] = lg;
    __syncthreads();      // sT loaded + rp visible

    float p0,p1,p2,p3,p4;
    int C = 0;
    float gold = 0.f;
    const int myM = m;

    if (!isB) {
        // ---------------- FORWARD: a_{m-1}, gold over [0,m) ----------------
        for (int t = g; t < m; t += 4) {
            int lt = lab[t];
            int lp = (t == 0) ? (LTOT-2) : lab[t-1];
            gold += lg[t*NLAB + lt] + sT[lt*LTOT + lp];
        }
        gold += __shfl_xor_sync(FULL, gold, 1, 4);
        gold += __shfl_xor_sync(FULL, gold, 2, 4);

        float w0[9], w1[9], w2[9];
        #pragma unroll
        for (int k = 0; k < 9; ++k) {
            int pr = cDP[k];
            w0[k] = expf(sT[s0*LTOT + pr]);
            w1[k] = expf(sT[(s0+1)*LTOT + pr]);
            w2[k] = (g==3) ? expf(sT[16*LTOT + pr]) : 0.f;
        }
        const float wIB = expf(sT[(s0+2)*LTOT + (s0+1)]);
        const float wII = expf(sT[(s0+2)*LTOT + (s0+2)]);
        const float wEB = expf(sT[(s0+3)*LTOT + (s0+1)]);
        const float wEI = expf(sT[(s0+3)*LTOT + (s0+2)]);

        {   // t = 0
            float wst4 = (g==3) ? expf(sT[16*LTOT + 17]) : 0.f;
            p0 = __expf(__ldg(lg+s0+0)) * expf(sT[s0*LTOT + 17]);
            p1 = __expf(__ldg(lg+s0+1)) * expf(sT[(s0+1)*LTOT + 17]);
            p2 = __expf(__ldg(lg+s0+2)) * expf(sT[(s0+2)*LTOT + 17]);
            p3 = __expf(__ldg(lg+s0+3)) * expf(sT[(s0+3)*LTOT + 17]);
            p4 = __expf(__ldg(lg+s0+4)) * wst4;
            RESC()
        }

        const int warpM = __reduce_max_sync(FULL, myM);
        const int nT = (warpM + 7) >> 3;

        stage_tile(rp, bufb, 0, lane);
        CPCOMMIT();

        for (int k = 0; k < nT; ++k) {
            int nxt = k + 1;
            if (nxt < nT) stage_tile(rp, bufb + (uint32_t)((nxt&1)*BUFF)*4u,
                                     nxt*8, lane);
            CPCOMMIT();
            CPWAIT1();
            __syncwarp();
            const float* cb = wbuf + (k&1)*BUFF;
            const int T0 = k*8;
            FSTEP(cb,0,T0+0) FSTEP(cb,1,T0+1) FSTEP(cb,2,T0+2) FSTEP(cb,3,T0+3)
            FSTEP(cb,4,T0+4) FSTEP(cb,5,T0+5) FSTEP(cb,6,T0+6) FSTEP(cb,7,T0+7)
            RESC()
        }

        float* sA = dyn + OFF_A + (q*8 + r)*20;
        sA[s0+0]=p0; sA[s0+1]=p1; sA[s0+2]=p2; sA[s0+3]=p3;
        if (g==3) sA[16]=p4;
        if (g==0) { dyn[OFF_G + q*8 + r] = gold;
                    ((int*)(dyn + OFF_C))[q*8 + r] = C; }
        asm volatile("bar.sync %0, %1;" :: "r"(1+q), "r"(64) : "memory");
    } else {
        // ---------------- BACKWARD: b_m, gold over [m,len) + end ----------
        for (int t = m + g; t < len; t += 4) {
            int lt = lab[t];
            gold += lg[t*NLAB + lt] + sT[lt*LTOT + lab[t-1]];
        }
        if (g==0) gold += sT[(LTOT-1)*LTOT + lab[len-1]];
        gold += __shfl_xor_sync(FULL, gold, 1, 4);
        gold += __shfl_xor_sync(FULL, gold, 2, 4);

        float w0[9], w1[9], w2[9];
        #pragma unroll
        for (int k = 0; k < 9; ++k) {
            int dt = cDT[k];
            w0[k] = expf(sT[dt*LTOT + s0]);
            w1[k] = expf(sT[dt*LTOT + (s0+3)]);
            w2[k] = (g==3) ? expf(sT[dt*LTOT + 16]) : 0.f;
        }
        const float wIB = expf(sT[(s0+2)*LTOT + (s0+1)]);
        const float wII = expf(sT[(s0+2)*LTOT + (s0+2)]);
        const float wEB = expf(sT[(s0+3)*LTOT + (s0+1)]);
        const float wEI = expf(sT[(s0+3)*LTOT + (s0+2)]);

        p0 = expf(sT[18*LTOT + s0]);
        p1 = expf(sT[18*LTOT + (s0+1)]);
        p2 = expf(sT[18*LTOT + (s0+2)]);
        p3 = expf(sT[18*LTOT + (s0+3)]);
        p4 = (g==3) ? expf(sT[18*LTOT + 16]) : 0.f;

        const int lenm1  = len - 1;
        const int warpT1 = __reduce_max_sync(FULL, lenm1);
        const int warpT0 = __reduce_min_sync(FULL, myM);
        const int kHi = warpT1 >> 3;
        const int kLo = warpT0 >> 3;

        stage_tile(rp, bufb + (uint32_t)((kHi&1)*BUFF)*4u, kHi*8, lane);
        CPCOMMIT();

        for (int k = kHi; k >= kLo; --k) {
            int nxt = k - 1;
            if (nxt >= kLo) stage_tile(rp, bufb + (uint32_t)((nxt&1)*BUFF)*4u,
                                       nxt*8, lane);
            CPCOMMIT();
            CPWAIT1();
            __syncwarp();
            const float* cb = wbuf + (k&1)*BUFF;
            const int T0 = k*8;
            BSTEP(cb,7,T0+7) BSTEP(cb,6,T0+6) BSTEP(cb,5,T0+5) BSTEP(cb,4,T0+4)
            BSTEP(cb,3,T0+3) BSTEP(cb,2,T0+2) BSTEP(cb,1,T0+1) BSTEP(cb,0,T0+0)
            RESC()
        }

        asm volatile("bar.sync %0, %1;" :: "r"(1+q), "r"(64) : "memory");

        const float* sA = dyn + OFF_A + (q*8 + r)*20;
        float ss = p0 * sA[s0+0];
        ss = fmaf(p1, sA[s0+1], ss);
        ss = fmaf(p2, sA[s0+2], ss);
        ss = fmaf(p3, sA[s0+3], ss);
        ss = fmaf(p4, sA[s0+4], ss);
        ss += __shfl_xor_sync(FULL, ss, 1, 4);
        ss += __shfl_xor_sync(FULL, ss, 2, 4);

        if (g==0 && valid) {
            float gT = gold + dyn[OFF_G + q*8 + r];
            int   cT = C + ((int*)(dyn + OFF_C))[q*8 + r];
            out[b] = gT - ((float)cT*LN2 + logf(ss));
        }
    }
}

extern "C" void kernel_launch(void* const* d_in, const int* in_sizes, int n_in,
                              void* d_out, int out_size)
{
    const float* logits     = (const float*)d_in[0];
    const int*   labels     = (const int*)  d_in[1];
    const int*   lens       = (const int*)  d_in[2];
    const float* transition = (const float*)d_in[3];
    float*       out        = (float*)d_out;

    int B = in_sizes[2];

    static int smem_set = 0;
    if (!smem_set) {
        cudaFuncSetAttribute(crf_main,
            cudaFuncAttributeMaxDynamicSharedMemorySize, SMEM_BYTES);
        smem_set = 1;
    }

    crf_sched<<<1, 1024>>>(lens, B);

    int nGroups = (B + 7) / 8;
    int grid = (nGroups + 3) / 4;
    if (grid < 148) grid = 148;
    crf_main<<<grid, 256, SMEM_BYTES>>>(logits, labels, lens, transition,
                                        out, B);
}

// round 15
// speedup vs baseline: 1.6075x; 1.5736x over previous
#include <cuda_runtime.h>
#include <math.h>

#define NLAB 17
#define LTOT 19
#define SEQ  256
#define MAXB 8192
#define LN2  0.69314718055994531f
#define FULL 0xffffffffu

__device__ int d_sorted[MAXB];

__constant__ signed char cDP[9] = {0,3,4,7,8,11,12,15,16};
__constant__ signed char cDT[9] = {0,1,4,5,8,9,12,13,16};

// One-block fused sort: histogram + warp-0 register suffix scan + scatter.
__global__ __launch_bounds__(1024)
void crf_sched(const int* __restrict__ lens, int B)
{
    __shared__ int h[SEQ];
    const int t = threadIdx.x;
    if (t < SEQ) h[t] = 0;
    __syncthreads();
    for (int i = t; i < B; i += 1024) atomicAdd(&h[lens[i] - 1], 1);
    __syncthreads();
    if (t < 32) {
        const int base = t * 8;
        int v[8]; int s = 0;
        #pragma unroll
        for (int k = 7; k >= 0; --k) { v[k] = s; s += h[base + k]; }
        int x = s;
        #pragma unroll
        for (int off = 1; off < 32; off <<= 1) {
            int y = __shfl_down_sync(FULL, x, off);
            if (t + off < 32) x += y;
        }
        int e = x - s;
        #pragma unroll
        for (int k = 0; k < 8; ++k) h[base + k] = v[k] + e;
    }
    __syncthreads();
    for (int i = t; i < B; i += 1024) {
        int r = atomicAdd(&h[lens[i] - 1], 1);
        d_sorted[r] = i;
    }
}

#define RESC() { \
    float _mx = fmaxf(fmaxf(p0,p1), fmaxf(p2, fmaxf(p3,p4))); \
    _mx = fmaxf(_mx, __shfl_xor_sync(FULL,_mx,1,4)); \
    _mx = fmaxf(_mx, __shfl_xor_sync(FULL,_mx,2,4)); \
    int _eb = (int)(__float_as_uint(_mx)>>23); \
    float _sc = __uint_as_float((unsigned)(254-_eb)<<23); \
    p0*=_sc; p1*=_sc; p2*=_sc; p3*=_sc; p4*=_sc; C += _eb-127; }

// Two aligned LDG.128 covering the lane's 8-float window at absolute step T.
// O must equal (T & 3) (literal at call site): 17T - O + 4g is a multiple of 4,
// and lgs (= row base + 4g floats) is 16B aligned, so the casts are legal.
#define FLOAD(R, T, O) { \
    const float4* _a = (const float4*)(lgs + ((T)*17 - (O))); \
    float4 _v0 = __ldg(_a); float4 _v1 = __ldg(_a + 1); \
    R[0]=_v0.x; R[1]=_v0.y; R[2]=_v0.z; R[3]=_v0.w; \
    R[4]=_v1.x; R[5]=_v1.y; R[6]=_v1.z; R[7]=_v1.w; }

// tree-form 9-wide dot products: 3 parallel partials -> depth ~20 cyc
#define DENSE9() \
    float _u0=fmaf(w0[3],_Q3, w0[0]*_Q0); \
    float _v0=fmaf(w0[4],_Q4, w0[1]*_Q1); \
    float _t0=fmaf(w0[5],_Q5, w0[2]*_Q2); \
    float _u1=fmaf(w1[3],_Q3, w1[0]*_Q0); \
    float _v1=fmaf(w1[4],_Q4, w1[1]*_Q1); \
    float _t1=fmaf(w1[5],_Q5, w1[2]*_Q2); \
    float _u2=fmaf(w2[3],_Q3, w2[0]*_Q0); \
    float _v2=fmaf(w2[4],_Q4, w2[1]*_Q1); \
    float _t2=fmaf(w2[5],_Q5, w2[2]*_Q2); \
    _u0=fmaf(w0[6],_Q6,_u0); _v0=fmaf(w0[7],_Q7,_v0); _t0=fmaf(w0[8],_Q8,_t0); \
    _u1=fmaf(w1[6],_Q6,_u1); _v1=fmaf(w1[7],_Q7,_v1); _t1=fmaf(w1[8],_Q8,_t1); \
    _u2=fmaf(w2[6],_Q6,_u2); _v2=fmaf(w2[7],_Q7,_v2); _t2=fmaf(w2[8],_Q8,_t2); \
    float _S0=(_u0+_v0)+_t0; \
    float _S1=(_u1+_v1)+_t1; \
    float _S2=(_u2+_v2)+_t2;

// forward step at absolute T (O = T&3 literal); active for 1 <= T < myM
#define FSTEP(R, T, O) { \
    float _e0=__expf(R[(O)+0]), _e1=__expf(R[(O)+1]), _e2=__expf(R[(O)+2]); \
    float _e3=__expf(R[(O)+3]), _e4=__expf(R[(O)+4]); \
    float _Q0=__shfl_sync(FULL,p0,base+0); \
    float _Q1=__shfl_sync(FULL,p3,base+0); \
    float _Q2=__shfl_sync(FULL,p0,base+1); \
    float _Q3=__shfl_sync(FULL,p3,base+1); \
    float _Q4=__shfl_sync(FULL,p0,base+2); \
    float _Q5=__shfl_sync(FULL,p3,base+2); \
    float _Q6=__shfl_sync(FULL,p0,base+3); \
    float _Q7=__shfl_sync(FULL,p3,base+3); \
    float _Q8=__shfl_sync(FULL,p4,base+3); \
    DENSE9() \
    float _nI = fmaf(wII,p2, wIB*p1); \
    float _nE = fmaf(wEI,p2, wEB*p1); \
    bool _act = ((T) >= 1) && ((T) < myM); \
    p0 = _act ? _e0*_S0 : p0; \
    p1 = _act ? _e1*_S1 : p1; \
    p2 = _act ? _e2*_nI : p2; \
    p3 = _act ? _e3*_nE : p3; \
    p4 = _act ? _e4*_S2 : p4; }

// backward step at absolute T (O = T&3 literal); active for myM <= T <= lenm1
#define BSTEP(R, T, O) { \
    float _u0l=p0*__expf(R[(O)+0]); \
    float _u1l=p1*__expf(R[(O)+1]); \
    float _u2l=p2*__expf(R[(O)+2]); \
    float _u3l=p3*__expf(R[(O)+3]); \
    float _u4l=p4*__expf(R[(O)+4]); \
    float _Q0=__shfl_sync(FULL,_u0l,base+0); \
    float _Q1=__shfl_sync(FULL,_u1l,base+0); \
    float _Q2=__shfl_sync(FULL,_u0l,base+1); \
    float _Q3=__shfl_sync(FULL,_u1l,base+1); \
    float _Q4=__shfl_sync(FULL,_u0l,base+2); \
    float _Q5=__shfl_sync(FULL,_u1l,base+2); \
    float _Q6=__shfl_sync(FULL,_u0l,base+3); \
    float _Q7=__shfl_sync(FULL,_u1l,base+3); \
    float _Q8=__shfl_sync(FULL,_u4l,base+3); \
    DENSE9() \
    float _nB = fmaf(wEB,_u3l, wIB*_u2l); \
    float _nI = fmaf(wEI,_u3l, wII*_u2l); \
    bool _act = ((T) >= myM) && ((T) <= lenm1); \
    p0 = _act ? _S0 : p0; \
    p1 = _act ? _nB : p1; \
    p2 = _act ? _nI : p2; \
    p3 = _act ? _S1 : p3; \
    p4 = _act ? _S2 : p4; }

// Block = 8 warps = 4 (fwd,bwd) MITM pairs, 8 rows/pair (4 lanes/row).
// Serpentine group assignment, grid=148. Loads: 2 aligned LDG.128 per step.
__global__ __launch_bounds__(256)
void crf_main(const float* __restrict__ logits,
              const int*   __restrict__ labels,
              const int*   __restrict__ lens,
              const float* __restrict__ transition,
              float* __restrict__ out, int B)
{
    __shared__ float sT[LTOT*LTOT];
    __shared__ float sA[4][8][20];
    __shared__ float sG[4][8];
    __shared__ int   sC[4][8];

    for (int i = threadIdx.x; i < LTOT*LTOT; i += 256) sT[i] = transition[i];
    __syncthreads();

    const int lane = threadIdx.x & 31;
    const int wId  = threadIdx.x >> 5;
    const int q    = wId >> 1;
    const bool isB = wId & 1;
    const int g    = lane & 3;
    const int r    = lane >> 2;
    const int base = lane & ~3;

    const int nG  = (B + 7) >> 3;
    const int per = gridDim.x;
    const int G   = q * per + ((q & 1) ? (per - 1 - (int)blockIdx.x)
                                       : (int)blockIdx.x);
    int rank = G * 8 + r;
    const bool valid = (G < nG) && (rank < B);
    if (!valid) rank = B - 1;
    const int b   = d_sorted[rank];
    const int len = lens[b];
    const int m   = (len + 1) >> 1;
    const int myM = m;

    const float* lg  = logits + (size_t)b * (SEQ*NLAB);
    const int*   lab = labels + (size_t)b * SEQ;
    const int    s0  = 4*g;
    const float* lgs = lg + s0;     // 16B aligned (4g floats from 16B-aligned row)

    float p0,p1,p2,p3,p4;
    int C = 0;
    float gold = 0.f;

    if (!isB) {
        // ---------------- FORWARD: a_{m-1}, gold over [0,m) ----------------
        for (int t = g; t < m; t += 4) {
            int lt = lab[t];
            int lp = (t == 0) ? (LTOT-2) : lab[t-1];
            gold += lg[t*NLAB + lt] + sT[lt*LTOT + lp];
        }
        gold += __shfl_xor_sync(FULL, gold, 1, 4);
        gold += __shfl_xor_sync(FULL, gold, 2, 4);

        float w0[9], w1[9], w2[9];
        #pragma unroll
        for (int k = 0; k < 9; ++k) {
            int pr = cDP[k];
            w0[k] = expf(sT[s0*LTOT + pr]);
            w1[k] = expf(sT[(s0+1)*LTOT + pr]);
            w2[k] = (g==3) ? expf(sT[16*LTOT + pr]) : 0.f;
        }
        const float wIB = expf(sT[(s0+2)*LTOT + (s0+1)]);
        const float wII = expf(sT[(s0+2)*LTOT + (s0+2)]);
        const float wEB = expf(sT[(s0+3)*LTOT + (s0+1)]);
        const float wEI = expf(sT[(s0+3)*LTOT + (s0+2)]);

        {   // t = 0
            float wst4 = (g==3) ? expf(sT[16*LTOT + 17]) : 0.f;
            p0 = __expf(__ldg(lgs+0)) * expf(sT[s0*LTOT + 17]);
            p1 = __expf(__ldg(lgs+1)) * expf(sT[(s0+1)*LTOT + 17]);
            p2 = __expf(__ldg(lgs+2)) * expf(sT[(s0+2)*LTOT + 17]);
            p3 = __expf(__ldg(lgs+3)) * expf(sT[(s0+3)*LTOT + 17]);
            p4 = __expf(__ldg(lgs+4)) * wst4;
            RESC()
        }

        const int warpM = __reduce_max_sync(FULL, myM);

        float RA[4][8], RB[4][8];
        FLOAD(RA[0],0,0) FLOAD(RA[1],1,1) FLOAD(RA[2],2,2) FLOAD(RA[3],3,3)
        for (int k = 0; k*8 < warpM; ++k) {
            const int t0 = k*8;
            FLOAD(RB[0],t0+4,0) FLOAD(RB[1],t0+5,1)
            FLOAD(RB[2],t0+6,2) FLOAD(RB[3],t0+7,3)
            FSTEP(RA[0],t0+0,0) FSTEP(RA[1],t0+1,1)
            FSTEP(RA[2],t0+2,2) FSTEP(RA[3],t0+3,3)
            FLOAD(RA[0],t0+8,0) FLOAD(RA[1],t0+9,1)
            FLOAD(RA[2],t0+10,2) FLOAD(RA[3],t0+11,3)
            FSTEP(RB[0],t0+4,0) FSTEP(RB[1],t0+5,1)
            FSTEP(RB[2],t0+6,2) FSTEP(RB[3],t0+7,3)
            RESC()
        }

        sA[q][r][s0+0]=p0; sA[q][r][s0+1]=p1;
        sA[q][r][s0+2]=p2; sA[q][r][s0+3]=p3;
        if (g==3) sA[q][r][16]=p4;
        if (g==0) { sG[q][r]=gold; sC[q][r]=C; }
        asm volatile("bar.sync %0, %1;" :: "r"(1+q), "r"(64) : "memory");
    } else {
        // ---------------- BACKWARD: b_m, gold over [m,len) + end ----------
        for (int t = m + g; t < len; t += 4) {
            int lt = lab[t];
            gold += lg[t*NLAB + lt] + sT[lt*LTOT + lab[t-1]];
        }
        if (g==0) gold += sT[(LTOT-1)*LTOT + lab[len-1]];
        gold += __shfl_xor_sync(FULL, gold, 1, 4);
        gold += __shfl_xor_sync(FULL, gold, 2, 4);

        float w0[9], w1[9], w2[9];
        #pragma unroll
        for (int k = 0; k < 9; ++k) {
            int dt = cDT[k];
            w0[k] = expf(sT[dt*LTOT + s0]);
            w1[k] = expf(sT[dt*LTOT + (s0+3)]);
            w2[k] = (g==3) ? expf(sT[dt*LTOT + 16]) : 0.f;
        }
        const float wIB = expf(sT[(s0+2)*LTOT + (s0+1)]);
        const float wII = expf(sT[(s0+2)*LTOT + (s0+2)]);
        const float wEB = expf(sT[(s0+3)*LTOT + (s0+1)]);
        const float wEI = expf(sT[(s0+3)*LTOT + (s0+2)]);

        p0 = expf(sT[18*LTOT + s0]);
        p1 = expf(sT[18*LTOT + (s0+1)]);
        p2 = expf(sT[18*LTOT + (s0+2)]);
        p3 = expf(sT[18*LTOT + (s0+3)]);
        p4 = (g==3) ? expf(sT[18*LTOT + 16]) : 0.f;

        const int lenm1  = len - 1;
        const int warpT1 = __reduce_max_sync(FULL, lenm1);
        const int tLow   = __reduce_min_sync(FULL, myM);
        const int kHi = warpT1 >> 3;
        const int kLo = tLow >> 3;

        float RA[4][8], RB[4][8];
        {
            const int t0 = kHi*8;
            FLOAD(RA[0],t0+7,3) FLOAD(RA[1],t0+6,2)
            FLOAD(RA[2],t0+5,1) FLOAD(RA[3],t0+4,0)
        }
        for (int k = kHi; k >= kLo; --k) {
            const int t0 = k*8;
            FLOAD(RB[0],t0+3,3) FLOAD(RB[1],t0+2,2)
            FLOAD(RB[2],t0+1,1) FLOAD(RB[3],t0+0,0)
            BSTEP(RA[0],t0+7,3) BSTEP(RA[1],t0+6,2)
            BSTEP(RA[2],t0+5,1) BSTEP(RA[3],t0+4,0)
            if (k > kLo) {
                const int t1 = t0 - 8;
                FLOAD(RA[0],t1+7,3) FLOAD(RA[1],t1+6,2)
                FLOAD(RA[2],t1+5,1) FLOAD(RA[3],t1+4,0)
            }
            BSTEP(RB[0],t0+3,3) BSTEP(RB[1],t0+2,2)
            BSTEP(RB[2],t0+1,1) BSTEP(RB[3],t0+0,0)
            RESC()
        }

        asm volatile("bar.sync %0, %1;" :: "r"(1+q), "r"(64) : "memory");

        float ss = p0 * sA[q][r][s0+0];
        ss = fmaf(p1, sA[q][r][s0+1], ss);
        ss = fmaf(p2, sA[q][r][s0+2], ss);
        ss = fmaf(p3, sA[q][r][s0+3], ss);
        ss = fmaf(p4, sA[q][r][s0+4], ss);
        ss += __shfl_xor_sync(FULL, ss, 1, 4);
        ss += __shfl_xor_sync(FULL, ss, 2, 4);

        if (g==0 && valid) {
            float gT = gold + sG[q][r];
            int   cT = C + sC[q][r];
            out[b] = gT - ((float)cT*LN2 + logf(ss));
        }
    }
}

extern "C" void kernel_launch(void* const* d_in, const int* in_sizes, int n_in,
                              void* d_out, int out_size)
{
    const float* logits     = (const float*)d_in[0];
    const int*   labels     = (const int*)  d_in[1];
    const int*   lens       = (const int*)  d_in[2];
    const float* transition = (const float*)d_in[3];
    float*       out        = (float*)d_out;

    int B = in_sizes[2];

    crf_sched<<<1, 1024>>>(lens, B);

    int nGroups = (B + 7) / 8;
    int grid = (nGroups + 3) / 4;
    if (grid < 148) grid = 148;
    crf_main<<<grid, 256>>>(logits, labels, lens, transition, out, B);
}